// round 6
// baseline (speedup 1.0000x reference)
#include <cuda_runtime.h>

#define B_   32
#define C_   256
#define H_   64
#define W_   64
#define HW_  4096            // H*W
#define BC_  8192            // B*C
#define HID_ 64
#define KSZ_ 5

#define CHUNK_B 8            // batches per pipeline chunk (32 MB of x)
#define NCHUNK  (B_ / CHUNK_B)

// Scratch (allocation-free rule: __device__ globals; zero-initialized at load)
__device__ float g_mean[BC_];
__device__ float g_h4v[BC_];    // 0.125 / (var + 1e-4)
__device__ float g_s2[BC_];     // sum over HW of x*sigmoid(energy)
__device__ float g_gate[BC_];   // ECA gate
__device__ float g_alpha[BC_];  // fusion gate
__device__ int   g_cnt[B_];     // per-batch arrival counters (self-resetting)

__device__ __forceinline__ float sigm(float v) {          // tiny gate math only
    return 1.0f / (1.0f + __expf(-v));
}
__device__ __forceinline__ float tanh_fast(float v) {     // MUFU.TANH, 1 MUFU
    float r;
    asm("tanh.approx.f32 %0, %1;" : "=f"(r) : "f"(v));
    return r;
}

// ---------------------------------------------------------------------------
// Kernel 1: per-(b,c) stats + SimAM-weighted sum for one chunk of batches,
// with the per-batch ECA+MLP gate fused in: the LAST CTA of each batch to
// arrive (atomic counter) computes gate+alpha for that batch.
// ---------------------------------------------------------------------------
__global__ void __launch_bounds__(256) stat_gate_kernel(const float* __restrict__ x,
                                                        const float* __restrict__ cw,
                                                        const float* __restrict__ w1,
                                                        const float* __restrict__ w2,
                                                        int b0)
{
    const int row = b0 * C_ + blockIdx.x;          // global (b*C + c)
    const int b   = row >> 8;
    const int t   = threadIdx.x;
    const float4* xr = (const float4*)(x + (size_t)row * HW_);

    float4 v[4];
#pragma unroll
    for (int j = 0; j < 4; j++) v[j] = xr[t + j * 256];

    float s = 0.f, ss = 0.f;
#pragma unroll
    for (int j = 0; j < 4; j++) {
        float4 q = v[j];
        s  += (q.x + q.y) + (q.z + q.w);
        ss += q.x * q.x + q.y * q.y + q.z * q.z + q.w * q.w;
    }
#pragma unroll
    for (int o = 16; o > 0; o >>= 1) {
        s  += __shfl_xor_sync(0xffffffffu, s,  o);
        ss += __shfl_xor_sync(0xffffffffu, ss, o);
    }

    __shared__ float shS[8], shQ[8], bcast[2];
    __shared__ int   sh_last;
    const int w = t >> 5, l = t & 31;
    if (l == 0) { shS[w] = s; shQ[w] = ss; }
    __syncthreads();
    if (t == 0) {
        float S = 0.f, Q = 0.f;
#pragma unroll
        for (int i = 0; i < 8; i++) { S += shS[i]; Q += shQ[i]; }
        const float mean = S * (1.0f / HW_);
        const float var  = (Q - (float)HW_ * mean * mean) * (1.0f / (HW_ - 1));
        const float h4v  = 0.125f / (var + 1e-4f);
        bcast[0] = mean; bcast[1] = h4v;
        g_mean[row] = mean;
        g_h4v[row]  = h4v;
    }
    __syncthreads();
    const float mean = bcast[0];
    const float h4v  = bcast[1];

    float s2 = 0.f;
#pragma unroll
    for (int j = 0; j < 4; j++) {
        float4 q = v[j];
        float d, th;
        d = q.x - mean; th = tanh_fast(fmaf(d * d, h4v, 0.25f)); s2 = fmaf(q.x, fmaf(th, 0.5f, 0.5f), s2);
        d = q.y - mean; th = tanh_fast(fmaf(d * d, h4v, 0.25f)); s2 = fmaf(q.y, fmaf(th, 0.5f, 0.5f), s2);
        d = q.z - mean; th = tanh_fast(fmaf(d * d, h4v, 0.25f)); s2 = fmaf(q.z, fmaf(th, 0.5f, 0.5f), s2);
        d = q.w - mean; th = tanh_fast(fmaf(d * d, h4v, 0.25f)); s2 = fmaf(q.w, fmaf(th, 0.5f, 0.5f), s2);
    }
#pragma unroll
    for (int o = 16; o > 0; o >>= 1)
        s2 += __shfl_xor_sync(0xffffffffu, s2, o);
    if (l == 0) shS[w] = s2;
    __syncthreads();
    if (t == 0) {
        float S = 0.f;
#pragma unroll
        for (int i = 0; i < 8; i++) S += shS[i];
        g_s2[row] = S;
        __threadfence();                               // release stats
        const int old = atomicAdd(&g_cnt[b], 1);
        sh_last = (old == C_ - 1);
    }
    __syncthreads();

    if (!sh_last) return;

    // ---- fused gate: this CTA is the last of batch b; all stats visible ----
    __threadfence();                                   // acquire
    const int c   = t;                                 // 0..255
    const int idx = b * C_ + c;

    __shared__ float m[C_], gap[C_], hid[HID_];
    m[c] = __ldcg(&g_mean[idx]);
    const float s2c = __ldcg(&g_s2[idx]);
    __syncthreads();

    float y = 0.f;
#pragma unroll
    for (int k = 0; k < KSZ_; k++) {
        const int cc = c + k - (KSZ_ - 1) / 2;
        const float mv = (cc >= 0 && cc < C_) ? m[cc] : 0.f;
        y = fmaf(mv, cw[k], y);
    }
    const float gate = sigm(y);
    g_gate[idx] = gate;
    gap[c] = fmaf(gate, m[c], s2c * (1.0f / HW_));
    __syncthreads();

    {   // hid[j] = relu(sum_c gap[c]*w1[j,c]); 4 threads per j
        const int j = c >> 2, p = c & 3;
        float h = 0.f;
        const float* w1r = w1 + j * C_ + p * 64;
        const float* gp  = gap + p * 64;
#pragma unroll 8
        for (int i = 0; i < 64; i++) h = fmaf(gp[i], w1r[i], h);
        h += __shfl_xor_sync(0xffffffffu, h, 1);
        h += __shfl_xor_sync(0xffffffffu, h, 2);
        if (p == 0) hid[j] = fmaxf(h, 0.f);
    }
    __syncthreads();

    float a = 0.f;
    const float* w2r = w2 + c * HID_;
#pragma unroll 8
    for (int j = 0; j < HID_; j++) a = fmaf(hid[j], w2r[j], a);
    g_alpha[idx] = sigm(a);

    if (t == 0) atomicExch(&g_cnt[b], 0);              // self-reset for next replay
}

// ---------------------------------------------------------------------------
// Kernel 2: out = x * (alpha*sigmoid(energy) + (1-alpha)*gate) for one chunk.
// Reads hit L2 (chunk just streamed by stat_gate_kernel); streaming stores.
// ---------------------------------------------------------------------------
__global__ void __launch_bounds__(256) out_kernel(const float* __restrict__ x,
                                                  float* __restrict__ out,
                                                  int b0)
{
    const int row = b0 * C_ + blockIdx.x;
    const int t   = threadIdx.x;

    const float mean  = g_mean[row];
    const float h4v   = g_h4v[row];
    const float alpha = g_alpha[row];
    const float a2    = 0.5f * alpha;
    const float a3    = fmaf(1.0f - alpha, g_gate[row], a2);

    const float4* xr = (const float4*)(x   + (size_t)row * HW_);
    float4*       ow = (float4*)     (out + (size_t)row * HW_);

    float4 q[4];
#pragma unroll
    for (int j = 0; j < 4; j++) q[j] = xr[t + j * 256];

#pragma unroll
    for (int j = 0; j < 4; j++) {
        float d, th;
        d = q[j].x - mean; th = tanh_fast(fmaf(d * d, h4v, 0.25f)); q[j].x = q[j].x * fmaf(a2, th, a3);
        d = q[j].y - mean; th = tanh_fast(fmaf(d * d, h4v, 0.25f)); q[j].y = q[j].y * fmaf(a2, th, a3);
        d = q[j].z - mean; th = tanh_fast(fmaf(d * d, h4v, 0.25f)); q[j].z = q[j].z * fmaf(a2, th, a3);
        d = q[j].w - mean; th = tanh_fast(fmaf(d * d, h4v, 0.25f)); q[j].w = q[j].w * fmaf(a2, th, a3);
    }

#pragma unroll
    for (int j = 0; j < 4; j++) __stcs(&ow[t + j * 256], q[j]);
}

// ---------------------------------------------------------------------------
extern "C" void kernel_launch(void* const* d_in, const int* in_sizes, int n_in,
                              void* d_out, int out_size)
{
    const float* x  = (const float*)d_in[0];   // [B, C, H, W]
    const float* cw = (const float*)d_in[1];   // [1, 1, 5]
    const float* w1 = (const float*)d_in[2];   // [HID, C]
    const float* w2 = (const float*)d_in[3];   // [C, HID]
    float* out = (float*)d_out;

    for (int k = 0; k < NCHUNK; k++) {
        const int b0 = k * CHUNK_B;
        stat_gate_kernel<<<CHUNK_B * C_, 256>>>(x, cw, w1, w2, b0);
        out_kernel<<<CHUNK_B * C_, 256>>>(x, out, b0);
    }
}

// round 7
// speedup vs baseline: 3.0720x; 3.0720x over previous
#include <cuda_runtime.h>

#define B_   32
#define C_   256
#define H_   64
#define W_   64
#define HW_  4096            // H*W
#define BC_  8192            // B*C
#define HID_ 64
#define KSZ_ 5

// Scratch (allocation-free rule: __device__ globals)
__device__ float g_mean[BC_];
__device__ float g_h4v[BC_];    // 0.125 / (var + 1e-4)
__device__ float g_s2[BC_];     // sum over HW of x*sigmoid(energy)
__device__ float g_gate[BC_];   // ECA gate
__device__ float g_alpha[BC_];  // fusion gate

__device__ __forceinline__ float sigm(float v) {          // tiny gate math only
    return 1.0f / (1.0f + __expf(-v));
}
__device__ __forceinline__ float tanh_fast(float v) {     // MUFU.TANH, 1 MUFU
    float r;
    asm("tanh.approx.f32 %0, %1;" : "=f"(r) : "f"(v));
    return r;
}

// ---------------------------------------------------------------------------
// Kernel 1: per-(b,c) stats + SimAM-weighted sum.
// 256 thr x 16 elems, MLP=4 front-batched loads; __launch_bounds__(256,8)
// forces <=32 regs so 8 CTAs/SM are resident (100% occ) while keeping MLP.
// ---------------------------------------------------------------------------
__global__ void __launch_bounds__(256, 8) stat_kernel(const float* __restrict__ x)
{
    const int row = blockIdx.x;                    // b*C + c
    const int t   = threadIdx.x;
    const float4* xr = (const float4*)(x + (size_t)row * HW_);

    float4 v[4];
#pragma unroll
    for (int j = 0; j < 4; j++) v[j] = xr[t + j * 256];

    float s = 0.f, ss = 0.f;
#pragma unroll
    for (int j = 0; j < 4; j++) {
        float4 q = v[j];
        s  += (q.x + q.y) + (q.z + q.w);
        ss += q.x * q.x + q.y * q.y + q.z * q.z + q.w * q.w;
    }
#pragma unroll
    for (int o = 16; o > 0; o >>= 1) {
        s  += __shfl_xor_sync(0xffffffffu, s,  o);
        ss += __shfl_xor_sync(0xffffffffu, ss, o);
    }

    __shared__ float shS[8], shQ[8], bcast[2];
    const int w = t >> 5, l = t & 31;
    if (l == 0) { shS[w] = s; shQ[w] = ss; }
    __syncthreads();
    if (t == 0) {
        float S = 0.f, Q = 0.f;
#pragma unroll
        for (int i = 0; i < 8; i++) { S += shS[i]; Q += shQ[i]; }
        const float mean = S * (1.0f / HW_);
        const float var  = (Q - (float)HW_ * mean * mean) * (1.0f / (HW_ - 1));
        const float h4v  = 0.125f / (var + 1e-4f);   // = 0.5 * 1/(4(var+eps))
        bcast[0] = mean; bcast[1] = h4v;
        g_mean[row] = mean;
        g_h4v[row]  = h4v;
    }
    __syncthreads();
    const float mean = bcast[0];
    const float h4v  = bcast[1];

    float s2 = 0.f;
#pragma unroll
    for (int j = 0; j < 4; j++) {
        float4 q = v[j];
        float d, th;
        d = q.x - mean; th = tanh_fast(fmaf(d * d, h4v, 0.25f)); s2 = fmaf(q.x, fmaf(th, 0.5f, 0.5f), s2);
        d = q.y - mean; th = tanh_fast(fmaf(d * d, h4v, 0.25f)); s2 = fmaf(q.y, fmaf(th, 0.5f, 0.5f), s2);
        d = q.z - mean; th = tanh_fast(fmaf(d * d, h4v, 0.25f)); s2 = fmaf(q.z, fmaf(th, 0.5f, 0.5f), s2);
        d = q.w - mean; th = tanh_fast(fmaf(d * d, h4v, 0.25f)); s2 = fmaf(q.w, fmaf(th, 0.5f, 0.5f), s2);
    }
#pragma unroll
    for (int o = 16; o > 0; o >>= 1)
        s2 += __shfl_xor_sync(0xffffffffu, s2, o);
    if (l == 0) shS[w] = s2;
    __syncthreads();
    if (t == 0) {
        float S = 0.f;
#pragma unroll
        for (int i = 0; i < 8; i++) S += shS[i];
        g_s2[row] = S;
    }
}

// ---------------------------------------------------------------------------
// Kernel 2: per-batch ECA conv + fusion MLP (tiny). One CTA per batch.
// ---------------------------------------------------------------------------
__global__ void __launch_bounds__(256) gate_kernel(const float* __restrict__ cw,
                                                   const float* __restrict__ w1,
                                                   const float* __restrict__ w2)
{
    const int b = blockIdx.x;
    const int c = threadIdx.x;        // 0..255
    const int idx = b * C_ + c;

    __shared__ float m[C_], gap[C_], hid[HID_];
    m[c] = g_mean[idx];
    __syncthreads();

    // ECA: cross-correlation over channel dim, zero-padded, K=5
    float y = 0.f;
#pragma unroll
    for (int k = 0; k < KSZ_; k++) {
        const int cc = c + k - (KSZ_ - 1) / 2;
        const float mv = (cc >= 0 && cc < C_) ? m[cc] : 0.f;
        y = fmaf(mv, cw[k], y);
    }
    const float gate = sigm(y);
    g_gate[idx] = gate;
    gap[c] = fmaf(gate, m[c], g_s2[idx] * (1.0f / HW_));
    __syncthreads();

    // hid[j] = relu(sum_c gap[c] * w1[j, c]); 4 threads per output j
    {
        const int j = c >> 2;          // 0..63
        const int p = c & 3;           // 0..3
        float h = 0.f;
        const float* w1r = w1 + j * C_ + p * 64;
        const float* gp  = gap + p * 64;
#pragma unroll 8
        for (int i = 0; i < 64; i++) h = fmaf(gp[i], w1r[i], h);
        h += __shfl_xor_sync(0xffffffffu, h, 1);
        h += __shfl_xor_sync(0xffffffffu, h, 2);
        if (p == 0) hid[j] = fmaxf(h, 0.f);
    }
    __syncthreads();

    // alpha[c] = sigmoid(sum_j hid[j] * w2[c, j]), w2 is [C, HID] row-major
    float a = 0.f;
    const float* w2r = w2 + c * HID_;
#pragma unroll 8
    for (int j = 0; j < HID_; j++) a = fmaf(hid[j], w2r[j], a);
    g_alpha[idx] = sigm(a);
}

// ---------------------------------------------------------------------------
// Kernel 3: out = x * (alpha*sigmoid(energy) + (1-alpha)*gate)
// 256 thr x 16 elems, 4 front-batched loads, 4 streaming stores.
// Reverse row order targets stat_kernel's L2-resident tail.
// __launch_bounds__(256,8) for full occupancy to cover mixed R/W latency.
// ---------------------------------------------------------------------------
__global__ void __launch_bounds__(256, 8) out_kernel(const float* __restrict__ x,
                                                     float* __restrict__ out)
{
    const int row = BC_ - 1 - blockIdx.x;
    const int t   = threadIdx.x;

    const float mean  = g_mean[row];
    const float h4v   = g_h4v[row];
    const float alpha = g_alpha[row];
    const float a2    = 0.5f * alpha;
    const float a3    = fmaf(1.0f - alpha, g_gate[row], a2);

    const float4* xr = (const float4*)(x   + (size_t)row * HW_);
    float4*       ow = (float4*)     (out + (size_t)row * HW_);

    float4 q[4];
#pragma unroll
    for (int j = 0; j < 4; j++) q[j] = xr[t + j * 256];

#pragma unroll
    for (int j = 0; j < 4; j++) {
        float d, th;
        d = q[j].x - mean; th = tanh_fast(fmaf(d * d, h4v, 0.25f)); q[j].x = q[j].x * fmaf(a2, th, a3);
        d = q[j].y - mean; th = tanh_fast(fmaf(d * d, h4v, 0.25f)); q[j].y = q[j].y * fmaf(a2, th, a3);
        d = q[j].z - mean; th = tanh_fast(fmaf(d * d, h4v, 0.25f)); q[j].z = q[j].z * fmaf(a2, th, a3);
        d = q[j].w - mean; th = tanh_fast(fmaf(d * d, h4v, 0.25f)); q[j].w = q[j].w * fmaf(a2, th, a3);
    }

#pragma unroll
    for (int j = 0; j < 4; j++) __stcs(&ow[t + j * 256], q[j]);
}

// ---------------------------------------------------------------------------
extern "C" void kernel_launch(void* const* d_in, const int* in_sizes, int n_in,
                              void* d_out, int out_size)
{
    const float* x  = (const float*)d_in[0];   // [B, C, H, W]
    const float* cw = (const float*)d_in[1];   // [1, 1, 5]
    const float* w1 = (const float*)d_in[2];   // [HID, C]
    const float* w2 = (const float*)d_in[3];   // [C, HID]
    float* out = (float*)d_out;

    stat_kernel<<<BC_, 256>>>(x);
    gate_kernel<<<B_, 256>>>(cw, w1, w2);
    out_kernel<<<BC_, 256>>>(x, out);
}